// round 3
// baseline (speedup 1.0000x reference)
#include <cuda_runtime.h>

static constexpr int NI = 64;    // items
static constexpr int NH = 256;   // hidden units
#define ARB_EPS 1e-3f

// Packed 2-wide fp32 FMA (Blackwell f32x2 pipe; 2 FMAs per instruction)
__device__ __forceinline__ unsigned long long ffma2(unsigned long long a,
                                                    unsigned long long b,
                                                    unsigned long long c) {
    unsigned long long d;
    asm("fma.rn.f32x2 %0, %1, %2, %3;" : "=l"(d) : "l"(a), "l"(b), "l"(c));
    return d;
}

__device__ __forceinline__ float2 up2(unsigned long long v) {
    float2 r;
    asm("mov.b64 {%0, %1}, %2;" : "=f"(r.x), "=f"(r.y) : "l"(v));
    return r;
}

__device__ __forceinline__ float clamp01(float x) {
    return fminf(fmaxf(x, 0.0f), 1.0f);
}

// Reference-order dot: single fp32 accumulator, FFMA chain in ascending k,
// then + w0 (mimics cuBLAS SGEMM + bias epilogue rounding).
__device__ __forceinline__ float dotseq(const unsigned long long* v,
                                        const float* wrow, float w0h) {
    float acc = 0.0f;
    #pragma unroll
    for (int q = 0; q < 32; q++) {
        float2 f = up2(v[q]);
        acc = __fmaf_rn(f.x, wrow[2 * q],     acc);
        acc = __fmaf_rn(f.y, wrow[2 * q + 1], acc);
    }
    return acc + w0h;
}

__global__ __launch_bounds__(256, 1)
void rochet_fp32_kernel(const float* __restrict__ V,
                        const float* __restrict__ W,
                        const float* __restrict__ w0,
                        float* __restrict__ alloc_out,
                        float* __restrict__ pay_out,
                        int B)
{
    // smem: W as 256 rows x 32 packed f32x2 (64 KB), then w0 (1 KB)
    extern __shared__ unsigned long long sh[];
    unsigned long long* Wp = sh;                                   // NH * 32 ull
    float* Wf = reinterpret_cast<float*>(sh);                      // same, as floats
    float* w0s = reinterpret_cast<float*>(sh + (NH * NI) / 2);     // NH floats

    const int tid = threadIdx.x;
    {
        const float4* src = reinterpret_cast<const float4*>(W);
        float4* dst = reinterpret_cast<float4*>(Wp);
        #pragma unroll 4
        for (int i = tid; i < (NH * NI) / 4; i += 256) dst[i] = src[i];
        if (tid < NH) w0s[tid] = w0[tid];
    }
    __syncthreads();

    const long long base = (long long)blockIdx.x * 512;
    const long long sA = base + tid;
    const long long sB = base + 256 + tid;
    const bool hasA = sA < (long long)B;
    const bool hasB = sB < (long long)B;

    // Each thread: two samples' valuation rows, packed as f32x2
    unsigned long long va[32], vb[32];
    #pragma unroll
    for (int i = 0; i < 32; i++) { va[i] = 0ULL; vb[i] = 0ULL; }
    if (hasA) {
        const ulonglong2* p = reinterpret_cast<const ulonglong2*>(V + sA * NI);
        #pragma unroll
        for (int i = 0; i < 16; i++) { ulonglong2 t = p[i]; va[2*i] = t.x; va[2*i+1] = t.y; }
    }
    if (hasB) {
        const ulonglong2* p = reinterpret_cast<const ulonglong2*>(V + sB * NI);
        #pragma unroll
        for (int i = 0; i < 16; i++) { ulonglong2 t = p[i]; vb[2*i] = t.x; vb[2*i+1] = t.y; }
    }

    float mA = -3.4e38f, mB = -3.4e38f;     // top-1 (packed order)
    float m2A = -3.4e38f, m2B = -3.4e38f;   // top-2 (packed order)
    int iA = 0, iB = 0, i2A = 0, i2B = 0;

    #pragma unroll 1
    for (int h = 0; h < NH; ++h) {
        const ulonglong2* wr = reinterpret_cast<const ulonglong2*>(Wp + h * 32);
        unsigned long long a0 = 0ULL, a1 = 0ULL, b0 = 0ULL, b1 = 0ULL;
        #pragma unroll
        for (int q = 0; q < 16; q++) {
            ulonglong2 w2 = wr[q];                 // LDS.128 broadcast
            a0 = ffma2(va[2*q],     w2.x, a0);
            a1 = ffma2(va[2*q + 1], w2.y, a1);
            b0 = ffma2(vb[2*q],     w2.x, b0);
            b1 = ffma2(vb[2*q + 1], w2.y, b1);
        }
        const float w0h = w0s[h];
        float2 xa0 = up2(a0), xa1 = up2(a1);
        float hA = ((xa0.x + xa0.y) + (xa1.x + xa1.y)) + w0h;
        float2 xb0 = up2(b0), xb1 = up2(b1);
        float hB = ((xb0.x + xb0.y) + (xb1.x + xb1.y)) + w0h;

        // top-2 tracking (strict > keeps first index on ties)
        if (hA > mA)       { m2A = mA; i2A = iA; mA = hA; iA = h; }
        else if (hA > m2A) { m2A = hA; i2A = h; }
        if (hB > mB)       { m2B = mB; i2B = iB; mB = hB; iB = h; }
        else if (hB > m2B) { m2B = hB; i2B = h; }
    }

    // --- arbitration: re-evaluate top-2 with REFERENCE-order fp32 rounding ---
    if (hasA && ((mA - m2A) < ARB_EPS || fabsf(mA) < ARB_EPS)) {
        float s1 = dotseq(va, Wf + iA  * NI, w0s[iA]);
        float s2 = dotseq(va, Wf + i2A * NI, w0s[i2A]);
        // winner per reference: larger value; tie -> lower index (argmax-first)
        if (s2 > s1 || (s2 == s1 && i2A < iA)) { iA = i2A; s1 = s2; }
        mA = s1;
    }
    if (hasB && ((mB - m2B) < ARB_EPS || fabsf(mB) < ARB_EPS)) {
        float s1 = dotseq(vb, Wf + iB  * NI, w0s[iB]);
        float s2 = dotseq(vb, Wf + i2B * NI, w0s[i2B]);
        if (s2 > s1 || (s2 == s1 && i2B < iB)) { iB = i2B; s1 = s2; }
        mB = s1;
    }

    // ---- epilogue sample A ----
    if (hasA) {
        float* orow = alloc_out + sA * NI;
        if (mA > 0.0f) {
            const float4* wrow = reinterpret_cast<const float4*>(W + (long long)iA * NI);
            float s = 0.0f;
            #pragma unroll
            for (int j = 0; j < 16; j++) {
                float4 wv = __ldg(wrow + j);
                wv.x = clamp01(wv.x); wv.y = clamp01(wv.y);
                wv.z = clamp01(wv.z); wv.w = clamp01(wv.w);
                float2 v0 = up2(va[2*j]);
                float2 v1 = up2(va[2*j + 1]);
                s += wv.x * v0.x + wv.y * v0.y + wv.z * v1.x + wv.w * v1.y;
                reinterpret_cast<float4*>(orow)[j] = wv;
            }
            float p = s - mA;
            pay_out[sA] = p > 0.0f ? p : 0.0f;
        } else {
            float4 z = make_float4(0.f, 0.f, 0.f, 0.f);
            #pragma unroll
            for (int j = 0; j < 16; j++) reinterpret_cast<float4*>(orow)[j] = z;
            pay_out[sA] = 0.0f;
        }
    }

    // ---- epilogue sample B ----
    if (hasB) {
        float* orow = alloc_out + sB * NI;
        if (mB > 0.0f) {
            const float4* wrow = reinterpret_cast<const float4*>(W + (long long)iB * NI);
            float s = 0.0f;
            #pragma unroll
            for (int j = 0; j < 16; j++) {
                float4 wv = __ldg(wrow + j);
                wv.x = clamp01(wv.x); wv.y = clamp01(wv.y);
                wv.z = clamp01(wv.z); wv.w = clamp01(wv.w);
                float2 v0 = up2(vb[2*j]);
                float2 v1 = up2(vb[2*j + 1]);
                s += wv.x * v0.x + wv.y * v0.y + wv.z * v1.x + wv.w * v1.y;
                reinterpret_cast<float4*>(orow)[j] = wv;
            }
            float p = s - mB;
            pay_out[sB] = p > 0.0f ? p : 0.0f;
        } else {
            float4 z = make_float4(0.f, 0.f, 0.f, 0.f);
            #pragma unroll
            for (int j = 0; j < 16; j++) reinterpret_cast<float4*>(orow)[j] = z;
            pay_out[sB] = 0.0f;
        }
    }
}

extern "C" void kernel_launch(void* const* d_in, const int* in_sizes, int n_in,
                              void* d_out, int out_size)
{
    const float* V  = (const float*)d_in[0];   // [B, 64]
    const float* W  = (const float*)d_in[1];   // [256, 64]
    const float* w0 = (const float*)d_in[2];   // [256]
    const int B = in_sizes[0] / NI;

    float* alloc_out = (float*)d_out;                          // [B, 64]
    float* pay_out   = (float*)d_out + (long long)B * NI;      // [B]

    const size_t shmem = (size_t)(NH * NI + NH) * sizeof(float);  // 66560 B
    cudaFuncSetAttribute(rochet_fp32_kernel,
                         cudaFuncAttributeMaxDynamicSharedMemorySize, (int)shmem);

    const int grid = (B + 511) / 512;
    rochet_fp32_kernel<<<grid, 256, shmem>>>(V, W, w0, alloc_out, pay_out, B);
}

// round 5
// speedup vs baseline: 1.0745x; 1.0745x over previous
#include <cuda_runtime.h>
#include <cuda_fp16.h>
#include <cstdint>

static constexpr int NI = 64;     // items (K)
static constexpr int NH = 256;    // hidden units (N)
static constexpr int TM = 128;    // rows per block
#define ARB_EPS  4e-4f
#define LO_SCALE 2048.0f
#define LO_INV   4.8828125e-4f    // 2^-11

// ---- smem layout (bytes) ----
static constexpr int OFF_AH   = 0;       // 128 x 64 f16 swizzled  = 16384
static constexpr int OFF_AL   = 16384;   // lo2                    = 16384
static constexpr int OFF_WH   = 32768;   // 256 x 64 f16 swizzled  = 32768
static constexpr int OFF_WL   = 65536;   //                        = 32768
static constexpr int OFF_W0   = 98304;   // 256 f32                = 1024
static constexpr int OFF_CAND = 99328;   // 128 rows x 4 x 16B     = 8192
static constexpr int SMEM_TOTAL = 107520;

// Pre-converted W (swizzled f16 hi/lo), written by prep kernel
__device__ __align__(16) uint32_t g_W16[2][8192];   // 2 x 32768 B

__device__ __forceinline__ uint32_t smem_u32(const void* p) {
    uint32_t a;
    asm("{ .reg .u64 t; cvta.to.shared.u64 t, %1; cvt.u32.u64 %0, t; }" : "=r"(a) : "l"(p));
    return a;
}
__device__ __forceinline__ uint32_t sw128(uint32_t off) { return off ^ ((off >> 3) & 0x70); }

__device__ __forceinline__ void ldsm_x4(uint32_t* r, uint32_t addr) {
    asm volatile("ldmatrix.sync.aligned.m8n8.x4.shared.b16 {%0,%1,%2,%3}, [%4];"
                 : "=r"(r[0]), "=r"(r[1]), "=r"(r[2]), "=r"(r[3]) : "r"(addr));
}
__device__ __forceinline__ void ldsm_x2(uint32_t* r, uint32_t addr) {
    asm volatile("ldmatrix.sync.aligned.m8n8.x2.shared.b16 {%0,%1}, [%2];"
                 : "=r"(r[0]), "=r"(r[1]) : "r"(addr));
}
__device__ __forceinline__ void mma16816(float* c, const uint32_t* a, const uint32_t* b) {
    asm volatile("mma.sync.aligned.m16n8k16.row.col.f32.f16.f16.f32 "
                 "{%0,%1,%2,%3}, {%4,%5,%6,%7}, {%8,%9}, {%0,%1,%2,%3};"
                 : "+f"(c[0]), "+f"(c[1]), "+f"(c[2]), "+f"(c[3])
                 : "r"(a[0]), "r"(a[1]), "r"(a[2]), "r"(a[3]), "r"(b[0]), "r"(b[1]));
}

// 8 consecutive floats -> uint4 of f16-hi pairs + uint4 of scaled f16-lo pairs
__device__ __forceinline__ void convert8(const float* f, uint4& hi, uint4& lo) {
    uint32_t h[4], l[4];
    #pragma unroll
    for (int i = 0; i < 4; i++) {
        const float a = f[2 * i], b = f[2 * i + 1];
        __half2 hh = __floats2half2_rn(a, b);
        float2 bk = __half22float2(hh);
        __half2 ll = __floats2half2_rn((a - bk.x) * LO_SCALE, (b - bk.y) * LO_SCALE);
        h[i] = reinterpret_cast<uint32_t&>(hh);
        l[i] = reinterpret_cast<uint32_t&>(ll);
    }
    hi = make_uint4(h[0], h[1], h[2], h[3]);
    lo = make_uint4(l[0], l[1], l[2], l[3]);
}

// Reference-order dot: single fp32 FMA chain, ascending k.
__device__ __forceinline__ float dot_seq(const float* __restrict__ Vrow,
                                         const float* __restrict__ Wrow) {
    float acc = 0.0f;
    #pragma unroll
    for (int q = 0; q < 16; q++) {
        float4 v = __ldg(reinterpret_cast<const float4*>(Vrow) + q);
        float4 w = __ldg(reinterpret_cast<const float4*>(Wrow) + q);
        acc = __fmaf_rn(v.x, w.x, acc);
        acc = __fmaf_rn(v.y, w.y, acc);
        acc = __fmaf_rn(v.z, w.z, acc);
        acc = __fmaf_rn(v.w, w.w, acc);
    }
    return acc;
}

// ---- prep: convert W to swizzled f16 hi/lo once ----
__global__ void prep_W_kernel(const float* __restrict__ W) {
    const int r = threadIdx.x;            // 256 threads, one W row each
    float f[8];
    #pragma unroll 1
    for (int q = 0; q < 8; q++) {
        *reinterpret_cast<float4*>(f)     = __ldg(reinterpret_cast<const float4*>(W + r * NI) + 2 * q);
        *reinterpret_cast<float4*>(f + 4) = __ldg(reinterpret_cast<const float4*>(W + r * NI) + 2 * q + 1);
        uint4 hi, lo;
        convert8(f, hi, lo);
        const uint32_t off = sw128((uint32_t)r * 128 + q * 16);
        *reinterpret_cast<uint4*>(reinterpret_cast<char*>(g_W16[0]) + off) = hi;
        *reinterpret_cast<uint4*>(reinterpret_cast<char*>(g_W16[1]) + off) = lo;
    }
}

__global__ __launch_bounds__(128)
void rochet_mma_kernel(const float* __restrict__ V,
                       const float* __restrict__ W,
                       const float* __restrict__ w0,
                       float* __restrict__ alloc_out,
                       float* __restrict__ pay_out,
                       int B)
{
    extern __shared__ char smem[];
    const uint32_t sbase = smem_u32(smem);
    const int tid = threadIdx.x;
    const int w   = tid >> 5;
    const int l   = tid & 31;
    float* w0s = reinterpret_cast<float*>(smem + OFF_W0);

    // ---- stage W (already converted+swizzled) and w0 ----
    {
        const uint4* src = reinterpret_cast<const uint4*>(g_W16);
        uint4* dst = reinterpret_cast<uint4*>(smem + OFF_WH);   // WH then WL contiguous
        #pragma unroll
        for (int i = 0; i < 32; i++) dst[tid + 128 * i] = src[tid + 128 * i];
        w0s[tid] = w0[tid];
        w0s[tid + 128] = w0[tid + 128];
    }

    // ---- stage A (V rows -> f16 hi/lo, swizzled) ----
    const long long base = (long long)blockIdx.x * TM;
    {
        const long long row = base + tid;
        float f[64];
        if (row < (long long)B) {
            const float4* src = reinterpret_cast<const float4*>(V + row * NI);
            #pragma unroll
            for (int q = 0; q < 16; q++) reinterpret_cast<float4*>(f)[q] = __ldg(src + q);
        } else {
            #pragma unroll
            for (int k = 0; k < 64; k++) f[k] = 0.0f;
        }
        #pragma unroll
        for (int q = 0; q < 8; q++) {
            uint4 hi, lo;
            convert8(f + 8 * q, hi, lo);
            const uint32_t off = sw128((uint32_t)tid * 128 + q * 16);
            *reinterpret_cast<uint4*>(smem + OFF_AH + off) = hi;
            *reinterpret_cast<uint4*>(smem + OFF_AL + off) = lo;
        }
    }
    __syncthreads();

    // ---- load A fragments (resident): 2 mtiles x 4 ksteps x {hi,lo} ----
    uint32_t ah[2][4][4], al[2][4][4];
    {
        const int arow = w * 32 + (l & 15);
        const uint32_t kgrp = (l >> 4) ? 16u : 0u;
        #pragma unroll
        for (int mt = 0; mt < 2; mt++)
            #pragma unroll
            for (int ks = 0; ks < 4; ks++) {
                const uint32_t off = sw128((uint32_t)(arow + mt * 16) * 128 + ks * 32 + kgrp);
                ldsm_x4(ah[mt][ks], sbase + OFF_AH + off);
                ldsm_x4(al[mt][ks], sbase + OFF_AL + off);
            }
    }

    // ---- main loop over 32 n-tiles ----
    float m1[4], m2[4];
    int   i1[4], i2[4];
    #pragma unroll
    for (int t = 0; t < 4; t++) { m1[t] = -3.4e38f; m2[t] = -3.4e38f; i1[t] = 0; i2[t] = 0; }

    const uint32_t bro = (uint32_t)(l & 7) * 128 + (((l >> 3) & 1) << 4);
    const int colb = 2 * (l & 3);

    #pragma unroll 1
    for (int nt = 0; nt < 32; nt++) {
        uint32_t bh[4][2], bl[4][2];
        #pragma unroll
        for (int ks = 0; ks < 4; ks++) {
            const uint32_t off = sw128((uint32_t)nt * 1024 + bro + ks * 32);
            ldsm_x2(bh[ks], sbase + OFF_WH + off);
            ldsm_x2(bl[ks], sbase + OFF_WL + off);
        }
        const int hbase = nt * 8 + colb;
        const float2 w0p = *reinterpret_cast<const float2*>(smem + OFF_W0 + hbase * 4);

        #pragma unroll
        for (int mt = 0; mt < 2; mt++) {
            float c[4] = {0.f, 0.f, 0.f, 0.f};
            float d[4] = {0.f, 0.f, 0.f, 0.f};
            #pragma unroll
            for (int ks = 0; ks < 4; ks++) mma16816(c, ah[mt][ks], bh[ks]);
            #pragma unroll
            for (int ks = 0; ks < 4; ks++) mma16816(d, ah[mt][ks], bl[ks]);
            #pragma unroll
            for (int ks = 0; ks < 4; ks++) mma16816(d, al[mt][ks], bh[ks]);

            const float v0 = __fmaf_rn(LO_INV, d[0], c[0]) + w0p.x;
            const float v1 = __fmaf_rn(LO_INV, d[1], c[1]) + w0p.y;
            const float v2 = __fmaf_rn(LO_INV, d[2], c[2]) + w0p.x;
            const float v3 = __fmaf_rn(LO_INV, d[3], c[3]) + w0p.y;
            const int t0 = 2 * mt, t1 = 2 * mt + 1;
            // strict > keeps first (lowest h) on ties; scan order is ascending h
            if (v0 > m1[t0]) { m2[t0]=m1[t0]; i2[t0]=i1[t0]; m1[t0]=v0; i1[t0]=hbase; }
            else if (v0 > m2[t0]) { m2[t0]=v0; i2[t0]=hbase; }
            if (v1 > m1[t0]) { m2[t0]=m1[t0]; i2[t0]=i1[t0]; m1[t0]=v1; i1[t0]=hbase+1; }
            else if (v1 > m2[t0]) { m2[t0]=v1; i2[t0]=hbase+1; }
            if (v2 > m1[t1]) { m2[t1]=m1[t1]; i2[t1]=i1[t1]; m1[t1]=v2; i1[t1]=hbase; }
            else if (v2 > m2[t1]) { m2[t1]=v2; i2[t1]=hbase; }
            if (v3 > m1[t1]) { m2[t1]=m1[t1]; i2[t1]=i1[t1]; m1[t1]=v3; i1[t1]=hbase+1; }
            else if (v3 > m2[t1]) { m2[t1]=v3; i2[t1]=hbase+1; }
        }
    }

    // ---- publish per-lane top-2 candidates (warp-local region) ----
    #pragma unroll
    for (int t = 0; t < 4; t++) {
        const int rl = (l >> 2) + 8 * t;                 // warp-local row of slot t
        uint4 pk;
        pk.x = __float_as_uint(m1[t]);
        pk.y = __float_as_uint(m2[t]);
        pk.z = (uint32_t)i1[t];
        pk.w = (uint32_t)i2[t];
        *reinterpret_cast<uint4*>(smem + OFF_CAND + ((w * 32 + rl) * 4 + (l & 3)) * 16) = pk;
    }
    __syncwarp();

    // ---- epilogue: one row per lane ----
    const int rl = (l >> 2) + 8 * (l & 3);
    const long long row = base + w * 32 + rl;
    if (row < (long long)B) {
        float cv[8]; int ch[8];
        #pragma unroll
        for (int q = 0; q < 4; q++) {
            const uint4 pk = *reinterpret_cast<const uint4*>(
                smem + OFF_CAND + ((w * 32 + rl) * 4 + q) * 16);
            cv[2 * q]     = __uint_as_float(pk.x); ch[2 * q]     = (int)pk.z;
            cv[2 * q + 1] = __uint_as_float(pk.y); ch[2 * q + 1] = (int)pk.w;
        }
        // approx top-1 (lower h on ties)
        float v1 = cv[0]; int h1 = ch[0];
        #pragma unroll
        for (int q = 1; q < 8; q++)
            if (cv[q] > v1 || (cv[q] == v1 && ch[q] < h1)) { v1 = cv[q]; h1 = ch[q]; }

        const float* Vrow = V + row * NI;
        float bestdot = dot_seq(Vrow, W + h1 * NI);
        float best = bestdot + w0s[h1];
        int bi = h1;
        const float thr = v1 - ARB_EPS;
        #pragma unroll 1
        for (int q = 0; q < 8; q++) {
            if (cv[q] >= thr && ch[q] != h1) {
                const float dd = dot_seq(Vrow, W + ch[q] * NI);
                const float s = dd + w0s[ch[q]];
                if (s > best || (s == best && ch[q] < bi)) { best = s; bi = ch[q]; bestdot = dd; }
            }
        }

        float* orow = alloc_out + row * NI;
        if (best > 0.0f) {
            const float4* wr = reinterpret_cast<const float4*>(W + bi * NI);
            #pragma unroll
            for (int q = 0; q < 16; q++) {
                float4 wv = __ldg(wr + q);
                wv.x = fminf(fmaxf(wv.x, 0.f), 1.f);
                wv.y = fminf(fmaxf(wv.y, 0.f), 1.f);
                wv.z = fminf(fmaxf(wv.z, 0.f), 1.f);
                wv.w = fminf(fmaxf(wv.w, 0.f), 1.f);
                reinterpret_cast<float4*>(orow)[q] = wv;
            }
            const float p = bestdot - best;     // == -w0[bi] up to fp32 rounding
            pay_out[row] = p > 0.0f ? p : 0.0f;
        } else {
            const float4 z = make_float4(0.f, 0.f, 0.f, 0.f);
            #pragma unroll
            for (int q = 0; q < 16; q++) reinterpret_cast<float4*>(orow)[q] = z;
            pay_out[row] = 0.0f;
        }
    }
}

extern "C" void kernel_launch(void* const* d_in, const int* in_sizes, int n_in,
                              void* d_out, int out_size)
{
    const float* V  = (const float*)d_in[0];   // [B, 64]
    const float* W  = (const float*)d_in[1];   // [256, 64]
    const float* w0 = (const float*)d_in[2];   // [256]
    const int B = in_sizes[0] / NI;

    float* alloc_out = (float*)d_out;                          // [B, 64]
    float* pay_out   = (float*)d_out + (long long)B * NI;      // [B]

    cudaFuncSetAttribute(rochet_mma_kernel,
                         cudaFuncAttributeMaxDynamicSharedMemorySize, SMEM_TOTAL);

    prep_W_kernel<<<1, 256>>>(W);
    const int grid = (B + TM - 1) / TM;
    rochet_mma_kernel<<<grid, TM, SMEM_TOTAL>>>(V, W, w0, alloc_out, pay_out, B);
}

// round 6
// speedup vs baseline: 2.2023x; 2.0496x over previous
#include <cuda_runtime.h>
#include <cuda_fp16.h>
#include <cstdint>

static constexpr int NI = 64;     // items (K)
static constexpr int NH = 256;    // hidden units (N)
static constexpr int TM = 256;    // rows per block
#define ARB_EPS  3e-3f
#define LO_SCALE 2048.0f
#define LO_INV   4.8828125e-4f    // 2^-11

// ---- smem layout (bytes) ----
static constexpr int OFF_WH   = 0;       // 256 x 64 f16 swizzled = 32768
static constexpr int OFF_WL   = 32768;   //                       = 32768
static constexpr int OFF_W0   = 65536;   // 256 f32               = 1024
static constexpr int OFF_CAND = 66560;   // 256 rows x 4 x 8B     = 8192
static constexpr int SMEM_TOTAL = 74752;

// Pre-converted W (swizzled f16 hi/lo), written by prep kernel
__device__ __align__(16) uint32_t g_W16[2][8192];   // 2 x 32768 B

__device__ __forceinline__ uint32_t smem_u32(const void* p) {
    uint32_t a;
    asm("{ .reg .u64 t; cvta.to.shared.u64 t, %1; cvt.u32.u64 %0, t; }" : "=r"(a) : "l"(p));
    return a;
}
__device__ __forceinline__ uint32_t sw128(uint32_t off) { return off ^ ((off >> 3) & 0x70); }

__device__ __forceinline__ void ldsm_x2(uint32_t* r, uint32_t addr) {
    asm volatile("ldmatrix.sync.aligned.m8n8.x2.shared.b16 {%0,%1}, [%2];"
                 : "=r"(r[0]), "=r"(r[1]) : "r"(addr));
}
__device__ __forceinline__ void mma16816(float* c, const uint32_t* a, const uint32_t* b) {
    asm volatile("mma.sync.aligned.m16n8k16.row.col.f32.f16.f16.f32 "
                 "{%0,%1,%2,%3}, {%4,%5,%6,%7}, {%8,%9}, {%0,%1,%2,%3};"
                 : "+f"(c[0]), "+f"(c[1]), "+f"(c[2]), "+f"(c[3])
                 : "r"(a[0]), "r"(a[1]), "r"(a[2]), "r"(a[3]), "r"(b[0]), "r"(b[1]));
}

// float2 -> packed f16 hi pair + scaled f16 lo pair
__device__ __forceinline__ void cvt2(float a, float b, uint32_t& hi, uint32_t& lo) {
    __half2 hh = __floats2half2_rn(a, b);
    float2 bk = __half22float2(hh);
    __half2 ll = __floats2half2_rn((a - bk.x) * LO_SCALE, (b - bk.y) * LO_SCALE);
    hi = reinterpret_cast<uint32_t&>(hh);
    lo = reinterpret_cast<uint32_t&>(ll);
}

// pack 8 floats -> uint4 hi + uint4 lo (prep kernel)
__device__ __forceinline__ void convert8(const float* f, uint4& hi, uint4& lo) {
    cvt2(f[0], f[1], hi.x, lo.x);
    cvt2(f[2], f[3], hi.y, lo.y);
    cvt2(f[4], f[5], hi.z, lo.z);
    cvt2(f[6], f[7], hi.w, lo.w);
}

// Reference-order dot: single fp32 FMA chain, ascending k.
__device__ __forceinline__ float dot_seq(const float* __restrict__ Vrow,
                                         const float* __restrict__ Wrow) {
    float acc = 0.0f;
    #pragma unroll
    for (int q = 0; q < 16; q++) {
        float4 v = __ldg(reinterpret_cast<const float4*>(Vrow) + q);
        float4 w = __ldg(reinterpret_cast<const float4*>(Wrow) + q);
        acc = __fmaf_rn(v.x, w.x, acc);
        acc = __fmaf_rn(v.y, w.y, acc);
        acc = __fmaf_rn(v.z, w.z, acc);
        acc = __fmaf_rn(v.w, w.w, acc);
    }
    return acc;
}

// value -> sortable key with (255-h) embedded in low 8 mantissa bits
__device__ __forceinline__ float make_key(float v, int h) {
    uint32_t b = (__float_as_uint(v) & 0xFFFFFF00u) | (uint32_t)(255 - h);
    return __uint_as_float(b);
}
__device__ __forceinline__ int key_h(float k) {
    return 255 - (int)(__float_as_uint(k) & 0xFFu);
}

// ---- prep: convert W to swizzled f16 hi/lo once ----
__global__ void prep_W_kernel(const float* __restrict__ W) {
    const int r = threadIdx.x;            // 256 threads, one W row each
    float f[8];
    #pragma unroll 1
    for (int q = 0; q < 8; q++) {
        *reinterpret_cast<float4*>(f)     = __ldg(reinterpret_cast<const float4*>(W + r * NI) + 2 * q);
        *reinterpret_cast<float4*>(f + 4) = __ldg(reinterpret_cast<const float4*>(W + r * NI) + 2 * q + 1);
        uint4 hi, lo;
        convert8(f, hi, lo);
        const uint32_t off = sw128((uint32_t)r * 128 + q * 16);
        *reinterpret_cast<uint4*>(reinterpret_cast<char*>(g_W16[0]) + off) = hi;
        *reinterpret_cast<uint4*>(reinterpret_cast<char*>(g_W16[1]) + off) = lo;
    }
}

__global__ __launch_bounds__(256, 2)
void rochet_mma_kernel(const float* __restrict__ V,
                       const float* __restrict__ W,
                       const float* __restrict__ w0,
                       float* __restrict__ alloc_out,
                       float* __restrict__ pay_out,
                       int B)
{
    extern __shared__ char smem[];
    const uint32_t sbase = smem_u32(smem);
    const int tid = threadIdx.x;
    const int w   = tid >> 5;
    const int l   = tid & 31;
    float* w0s = reinterpret_cast<float*>(smem + OFF_W0);

    // ---- stage W (pre-converted + swizzled) and w0 ----
    {
        const uint4* src = reinterpret_cast<const uint4*>(g_W16);
        uint4* dst = reinterpret_cast<uint4*>(smem + OFF_WH);
        #pragma unroll
        for (int i = 0; i < 16; i++) dst[tid + 256 * i] = src[tid + 256 * i];
        w0s[tid] = w0[tid];
    }

    // ---- build A fragments directly from gmem ----
    const long long base = (long long)blockIdx.x * TM;
    uint32_t ah[2][4][4], al[2][4][4];
    {
        const int r0 = w * 32 + (l >> 2);
        const int k0 = (l & 3) * 2;
        #pragma unroll
        for (int mt = 0; mt < 2; mt++)
            #pragma unroll
            for (int j = 0; j < 4; j++) {
                const long long row = base + r0 + mt * 16 + (j & 1) * 8;
                const int kb = k0 + (j >> 1) * 8;
                if (row < (long long)B) {
                    const float2* p = reinterpret_cast<const float2*>(V + row * NI + kb);
                    #pragma unroll
                    for (int ks = 0; ks < 4; ks++) {
                        const float2 v = __ldg(p + ks * 8);   // +16 floats per kstep
                        cvt2(v.x, v.y, ah[mt][ks][j], al[mt][ks][j]);
                    }
                } else {
                    #pragma unroll
                    for (int ks = 0; ks < 4; ks++) { ah[mt][ks][j] = 0u; al[mt][ks][j] = 0u; }
                }
            }
    }
    __syncthreads();

    // ---- main loop over 32 n-tiles ----
    float m1[4], m2[4];
    #pragma unroll
    for (int t = 0; t < 4; t++) { m1[t] = -3.4e38f; m2[t] = -3.4e38f; }

    const uint32_t bro = (uint32_t)(l & 7) * 128 + (((l >> 3) & 1) << 4);
    const int colb = 2 * (l & 3);

    #pragma unroll 2
    for (int nt = 0; nt < 32; nt++) {
        uint32_t bh[4][2], bl[4][2];
        #pragma unroll
        for (int ks = 0; ks < 4; ks++) {
            const uint32_t off = sw128((uint32_t)nt * 1024 + bro + ks * 32);
            ldsm_x2(bh[ks], sbase + OFF_WH + off);
            ldsm_x2(bl[ks], sbase + OFF_WL + off);
        }
        const int hbase = nt * 8 + colb;
        const float2 w0p = *reinterpret_cast<const float2*>(smem + OFF_W0 + hbase * 4);

        #pragma unroll
        for (int mt = 0; mt < 2; mt++) {
            float c[4] = {0.f, 0.f, 0.f, 0.f};
            float d[4] = {0.f, 0.f, 0.f, 0.f};
            #pragma unroll
            for (int ks = 0; ks < 4; ks++) mma16816(c, ah[mt][ks], bh[ks]);
            #pragma unroll
            for (int ks = 0; ks < 4; ks++) mma16816(d, ah[mt][ks], bl[ks]);
            #pragma unroll
            for (int ks = 0; ks < 4; ks++) mma16816(d, al[mt][ks], bh[ks]);

            const float k0 = make_key(__fmaf_rn(LO_INV, d[0], c[0]) + w0p.x, hbase);
            const float k1 = make_key(__fmaf_rn(LO_INV, d[1], c[1]) + w0p.y, hbase + 1);
            const float k2 = make_key(__fmaf_rn(LO_INV, d[2], c[2]) + w0p.x, hbase);
            const float k3 = make_key(__fmaf_rn(LO_INV, d[3], c[3]) + w0p.y, hbase + 1);
            const int s0 = 2 * mt, s1 = 2 * mt + 1;
            float t0 = fminf(m1[s0], k0); m1[s0] = fmaxf(m1[s0], k0); m2[s0] = fmaxf(m2[s0], t0);
            float t1 = fminf(m1[s0], k1); m1[s0] = fmaxf(m1[s0], k1); m2[s0] = fmaxf(m2[s0], t1);
            float t2 = fminf(m1[s1], k2); m1[s1] = fmaxf(m1[s1], k2); m2[s1] = fmaxf(m2[s1], t2);
            float t3 = fminf(m1[s1], k3); m1[s1] = fmaxf(m1[s1], k3); m2[s1] = fmaxf(m2[s1], t3);
        }
    }

    // ---- publish per-lane top-2 keys: cand[row_in_cta][l&3] ----
    #pragma unroll
    for (int mt = 0; mt < 2; mt++)
        #pragma unroll
        for (int rh = 0; rh < 2; rh++) {
            const int rc = w * 32 + mt * 16 + rh * 8 + (l >> 2);
            const int st = 2 * mt + rh;
            float2 pk = make_float2(m1[st], m2[st]);
            *reinterpret_cast<float2*>(smem + OFF_CAND + (rc * 4 + (l & 3)) * 8) = pk;
        }
    __syncwarp();

    // ---- epilogue: thread tid handles row tid (same warp wrote its cand) ----
    const long long row = base + tid;
    if (row < (long long)B) {
        float ck[8];
        #pragma unroll
        for (int q = 0; q < 4; q++) {
            const float2 pk = *reinterpret_cast<const float2*>(smem + OFF_CAND + (tid * 4 + q) * 8);
            ck[2 * q] = pk.x; ck[2 * q + 1] = pk.y;
        }
        float kbest = ck[0];
        #pragma unroll
        for (int q = 1; q < 8; q++) kbest = fmaxf(kbest, ck[q]);
        const int h1 = key_h(kbest);

        const float* Vrow = V + row * NI;
        float bestdot = dot_seq(Vrow, W + h1 * NI);
        float best = bestdot + w0s[h1];
        int bi = h1;
        const float thr = kbest - ARB_EPS;
        #pragma unroll 1
        for (int q = 0; q < 8; q++) {
            const int hq = key_h(ck[q]);
            if (ck[q] >= thr && hq != h1) {
                const float dd = dot_seq(Vrow, W + hq * NI);
                const float s = dd + w0s[hq];
                if (s > best || (s == best && hq < bi)) { best = s; bi = hq; bestdot = dd; }
            }
        }

        float* orow = alloc_out + row * NI;
        if (best > 0.0f) {
            const float4* wr = reinterpret_cast<const float4*>(W + bi * NI);
            #pragma unroll
            for (int q = 0; q < 16; q++) {
                float4 wv = __ldg(wr + q);
                wv.x = fminf(fmaxf(wv.x, 0.f), 1.f);
                wv.y = fminf(fmaxf(wv.y, 0.f), 1.f);
                wv.z = fminf(fmaxf(wv.z, 0.f), 1.f);
                wv.w = fminf(fmaxf(wv.w, 0.f), 1.f);
                reinterpret_cast<float4*>(orow)[q] = wv;
            }
            const float p = bestdot - best;
            pay_out[row] = p > 0.0f ? p : 0.0f;
        } else {
            const float4 z = make_float4(0.f, 0.f, 0.f, 0.f);
            #pragma unroll
            for (int q = 0; q < 16; q++) reinterpret_cast<float4*>(orow)[q] = z;
            pay_out[row] = 0.0f;
        }
    }
}

extern "C" void kernel_launch(void* const* d_in, const int* in_sizes, int n_in,
                              void* d_out, int out_size)
{
    const float* V  = (const float*)d_in[0];   // [B, 64]
    const float* W  = (const float*)d_in[1];   // [256, 64]
    const float* w0 = (const float*)d_in[2];   // [256]
    const int B = in_sizes[0] / NI;

    float* alloc_out = (float*)d_out;                          // [B, 64]
    float* pay_out   = (float*)d_out + (long long)B * NI;      // [B]

    cudaFuncSetAttribute(rochet_mma_kernel,
                         cudaFuncAttributeMaxDynamicSharedMemorySize, SMEM_TOTAL);

    prep_W_kernel<<<1, 256>>>(W);
    const int grid = (B + TM - 1) / TM;
    rochet_mma_kernel<<<grid, 256, SMEM_TOTAL>>>(V, W, w0, alloc_out, pay_out, B);
}